// round 4
// baseline (speedup 1.0000x reference)
#include <cuda_runtime.h>
#include <cuda_bf16.h>
#include <cuda_fp16.h>
#include <cstdint>

#define N_NODES 100000
#define E_EDGES 3200000
#define F_INDIM 512
#define H_DIM   128
#define C_OUT   40

// ---------------- device scratch ----------------
__device__ __align__(16) float   g_h[N_NODES * H_DIM];
__device__ __align__(16) __half2 g_tmph[N_NODES * 64];
__device__ __align__(16) float   g_wide[N_NODES * C_OUT];
__device__ float g_attn0[N_NODES];
__device__ float g_dinv[N_NODES];
__device__ int   g_counts[N_NODES];
__device__ int   g_offsets[N_NODES];
__device__ int   g_cursor[N_NODES];
__device__ int   g_csr_row[E_EDGES];
__device__ float g_csr_val[E_EDGES];
__device__ int   g_partials[32];
__device__ int   g_is64;
__device__ __align__(16) float g_W2p[H_DIM * 48];
__device__ __align__(16) float g_bias192[192];
// B operands, tripled-K layout [n][3K]: [0,K)=hi, [K,2K)=hi, [2K,3K)=lo
__device__ __align__(16) unsigned short g_Bl1[192 * 1536];
__device__ __align__(16) unsigned short g_Bc1[128 * 384];
__device__ __align__(16) unsigned short g_Bc2[128 * 384];

// ---------------- small helpers ----------------
__device__ __forceinline__ void split_bf16(float v, unsigned short& h, unsigned short& l) {
    __nv_bfloat16 hb = __float2bfloat16(v);
    __nv_bfloat16 lb = __float2bfloat16(v - __bfloat162float(hb));
    h = *(unsigned short*)&hb; l = *(unsigned short*)&lb;
}
__device__ __forceinline__ uint32_t s2u(const void* p) {
    uint32_t a;
    asm("{ .reg .u64 t; cvta.to.shared.u64 t, %1; cvt.u32.u64 %0, t; }" : "=r"(a) : "l"(p));
    return a;
}
__device__ __forceinline__ void ldsm4(uint32_t* d, uint32_t addr) {
    asm volatile("ldmatrix.sync.aligned.m8n8.x4.shared.b16 {%0,%1,%2,%3}, [%4];"
                 : "=r"(d[0]), "=r"(d[1]), "=r"(d[2]), "=r"(d[3]) : "r"(addr));
}
__device__ __forceinline__ void mma16816(float* c, const uint32_t* a, const uint32_t* b) {
    asm volatile("mma.sync.aligned.m16n8k16.row.col.f32.bf16.bf16.f32 "
        "{%0,%1,%2,%3}, {%4,%5,%6,%7}, {%8,%9}, {%0,%1,%2,%3};"
        : "+f"(c[0]), "+f"(c[1]), "+f"(c[2]), "+f"(c[3])
        : "r"(a[0]), "r"(a[1]), "r"(a[2]), "r"(a[3]), "r"(b[0]), "r"(b[1]));
}

// ---------------- dtype detect / edge prep ----------------
__global__ void k_detect(const unsigned* __restrict__ ei_raw) {
    if (threadIdx.x == 0) g_is64 = 1;
    __syncthreads();
    unsigned v = ei_raw[2 * (threadIdx.x * 997 + 1) + 1];
    if (v != 0) atomicAnd(&g_is64, 0);
}
__device__ __forceinline__ void load_edge(const void* ei, int e, int is64, int& row, int& col) {
    if (is64) {
        const long long* p = (const long long*)ei;
        row = (int)p[e]; col = (int)p[E_EDGES + e];
    } else {
        const int* p = (const int*)ei;
        row = p[e]; col = p[E_EDGES + e];
    }
}
__global__ void k_init() {
    int n = blockIdx.x * blockDim.x + threadIdx.x;
    if (n < N_NODES) { g_dinv[n] = 1.0f; g_counts[n] = 0; }
}
__global__ void k_edge_deg(const void* __restrict__ ei, const float* __restrict__ ew) {
    int e = blockIdx.x * blockDim.x + threadIdx.x;
    if (e >= E_EDGES) return;
    int row, col;
    load_edge(ei, e, g_is64, row, col);
    atomicAdd(&g_dinv[col], ew[e]);
    atomicAdd(&g_counts[col], 1);
}
__global__ void k_rsqrt() {
    int n = blockIdx.x * blockDim.x + threadIdx.x;
    if (n < N_NODES) g_dinv[n] = rsqrtf(g_dinv[n]);
}
__global__ void k_scan1() {
    int t = threadIdx.x;
    int base = blockIdx.x * 4096 + t * 16;
    int vals[16]; int tot = 0;
#pragma unroll
    for (int i = 0; i < 16; i++) {
        int idx = base + i;
        int v = (idx < N_NODES) ? g_counts[idx] : 0;
        vals[i] = v; tot += v;
    }
    int lane = t & 31, w = t >> 5;
    int inc = tot;
#pragma unroll
    for (int o = 1; o < 32; o <<= 1) {
        int x = __shfl_up_sync(0xffffffffu, inc, o);
        if (lane >= o) inc += x;
    }
    __shared__ int wsum[8], wexc[8];
    if (lane == 31) wsum[w] = inc;
    __syncthreads();
    if (t == 0) {
        int run = 0;
        for (int i = 0; i < 8; i++) { wexc[i] = run; run += wsum[i]; }
        g_partials[blockIdx.x] = run;
    }
    __syncthreads();
    int run = wexc[w] + inc - tot;
#pragma unroll
    for (int i = 0; i < 16; i++) {
        int idx = base + i;
        if (idx < N_NODES) g_offsets[idx] = run;
        run += vals[i];
    }
}
__global__ void k_scan2() {
    int run = 0;
    for (int b = 0; b < 25; b++) { int v = g_partials[b]; g_partials[b] = run; run += v; }
}
__global__ void k_scan3() {
    int idx = blockIdx.x * blockDim.x + threadIdx.x;
    if (idx < N_NODES) {
        int o = g_offsets[idx] + g_partials[idx / 4096];
        g_offsets[idx] = o;
        g_cursor[idx] = o;
    }
}
__global__ void k_place(const void* __restrict__ ei, const float* __restrict__ ew) {
    int e = blockIdx.x * blockDim.x + threadIdx.x;
    if (e >= E_EDGES) return;
    int row, col;
    load_edge(ei, e, g_is64, row, col);
    int p = atomicAdd(&g_cursor[col], 1);
    g_csr_row[p] = row;
    g_csr_val[p] = g_dinv[row] * ew[e] * g_dinv[col];
}

// ---------------- weight packing (tripled-K B operands) ----------------
__global__ void k_packB_l1(const float* __restrict__ W1, const float* __restrict__ Ww,
                           const float* __restrict__ Wa) {
    int e = blockIdx.x * blockDim.x + threadIdx.x;
    if (e >= 192 * 512) return;
    int n = e / 512, k = e % 512;
    float v = 0.0f;
    if (n < 128) v = W1[k * 128 + n];
    else if (n < 168) v = Ww[k * 40 + (n - 128)];
    else if (n < 170) v = Wa[k * 2 + (n - 168)];
    unsigned short hb, lb; split_bf16(v, hb, lb);
    size_t base = (size_t)n * 1536;
    g_Bl1[base + k]        = hb;
    g_Bl1[base + 512 + k]  = hb;
    g_Bl1[base + 1024 + k] = lb;
}
__global__ void k_packB_conv(const float* __restrict__ W, unsigned short* __restrict__ dst) {
    int e = blockIdx.x * blockDim.x + threadIdx.x;
    if (e >= 128 * 128) return;
    int n = e / 128, k = e % 128;
    unsigned short hb, lb; split_bf16(W[k * 128 + n], hb, lb);
    size_t base = (size_t)n * 384;
    dst[base + k]       = hb;
    dst[base + 128 + k] = hb;
    dst[base + 256 + k] = lb;
}
__global__ void k_pack(const float* __restrict__ W2, const float* __restrict__ b1,
                       const float* __restrict__ bw, const float* __restrict__ ba) {
    int i = blockIdx.x * blockDim.x + threadIdx.x;
    if (i < H_DIM * 48) {
        int k = i / 48, c = i % 48;
        g_W2p[i] = (c < 40) ? W2[k * 40 + c] : 0.0f;
    }
    if (i < 192)
        g_bias192[i] = (i < 128) ? b1[i] : ((i < 168) ? bw[i - 128] : ((i < 170) ? ba[i - 168] : 0.0f));
}

// ---------------- mma.sync GEMM ----------------
// CTA tile 128 x (NF*16), 8 warps (4 M x 2 N), warp tile 32 x (NF*8).
// A: [M,KSRC] fp32, split to bf16 hi/lo in SMEM over tripled K' = KP.
// EPI 0: fused layer1 (N=192: h relu cols<128, wide 128-167, attn 168-169)
// EPI 1: conv -> g_tmph fp16
template<int NF, int KP, int EPI>
__global__ __launch_bounds__(256, 2) void gemm_mma(
    const float* __restrict__ A, const unsigned short* __restrict__ Bp, int KSRC)
{
    constexpr int NTILE = NF * 16;
    constexpr int BUFH = (128 + NTILE) * 72;   // halfs per buffer
    constexpr int CHUNKS = KP / 64;
    extern __shared__ __align__(16) unsigned short smu[];
    const int tid = threadIdx.x, lane = tid & 31, wid = tid >> 5;
    const int wm = wid >> 1, wn = wid & 1;
    const int Mbase = blockIdx.x * 128;
    const int nbase = blockIdx.y * NTILE;

    float acc[2][NF][4];
#pragma unroll
    for (int i = 0; i < 2; i++)
#pragma unroll
        for (int j = 0; j < NF; j++)
#pragma unroll
            for (int q = 0; q < 4; q++) acc[i][j][q] = 0.0f;

    auto fill = [&](int c, int buf) {
        unsigned short* smA = smu + buf * BUFH;
        unsigned short* smB = smA + 128 * 72;
        const int kq = c * 64;
        const bool lo = ((kq / KSRC) == 1);
        const int srck = kq % KSRC;
        // A: 128 x 64 fp32 -> bf16 (hi or lo)
        const int m = tid >> 1, half = tid & 1;
        const bool ok = (Mbase + m) < N_NODES;
        const float* Arow = A + (size_t)(Mbase + m) * KSRC + srck + half * 32;
        uint32_t* dst = (uint32_t*)(smA + m * 72 + half * 32);
#pragma unroll
        for (int i = 0; i < 8; i++) {
            float4 v = ok ? *(const float4*)(Arow + i * 4) : make_float4(0, 0, 0, 0);
            unsigned short hx, lx, hy, ly, hz, lz, hw, lw;
            split_bf16(v.x, hx, lx); split_bf16(v.y, hy, ly);
            split_bf16(v.z, hz, lz); split_bf16(v.w, hw, lw);
            uint32_t u0, u1;
            if (lo) { u0 = lx | ((uint32_t)ly << 16); u1 = lz | ((uint32_t)lw << 16); }
            else    { u0 = hx | ((uint32_t)hy << 16); u1 = hz | ((uint32_t)hw << 16); }
            dst[i * 2] = u0; dst[i * 2 + 1] = u1;
        }
        // B copy: NTILE rows x 64 halfs
#pragma unroll
        for (int idx = tid; idx < NTILE * 8; idx += 256) {
            int r = idx >> 3, seg = idx & 7;
            uint4 v = *(const uint4*)(Bp + (size_t)(nbase + r) * KP + kq + seg * 8);
            *(uint4*)(smB + r * 72 + seg * 8) = v;
        }
    };

    auto compute = [&](int buf) {
        unsigned short* smA = smu + buf * BUFH;
        unsigned short* smB = smA + 128 * 72;
        uint32_t aB = s2u(smA), bB = s2u(smB);
#pragma unroll
        for (int step = 0; step < 4; step++) {
            const int kk = step * 16;
            uint32_t a[2][4];
            {
                int r = (lane & 7) + ((lane & 8) ? 8 : 0);
                int col = kk + ((lane & 16) ? 8 : 0);
#pragma unroll
                for (int mf = 0; mf < 2; mf++) {
                    uint32_t addr = aB + (uint32_t)(((wm * 32 + mf * 16 + r) * 72 + col) * 2);
                    ldsm4(a[mf], addr);
                }
            }
            uint32_t b[NF][2];
            {
                int r = (lane & 7) + ((lane & 16) ? 8 : 0);
                int col = kk + ((lane & 8) ? 8 : 0);
#pragma unroll
                for (int np = 0; np < NF / 2; np++) {
                    uint32_t t[4];
                    uint32_t addr = bB + (uint32_t)(((wn * NF * 8 + np * 16 + r) * 72 + col) * 2);
                    ldsm4(t, addr);
                    b[2 * np][0] = t[0]; b[2 * np][1] = t[1];
                    b[2 * np + 1][0] = t[2]; b[2 * np + 1][1] = t[3];
                }
            }
#pragma unroll
            for (int mf = 0; mf < 2; mf++)
#pragma unroll
                for (int nf = 0; nf < NF; nf++)
                    mma16816(acc[mf][nf], a[mf], b[nf]);
        }
    };

    fill(0, 0);
    __syncthreads();
    for (int c = 0; c < CHUNKS; c++) {
        if (c + 1 < CHUNKS) fill(c + 1, (c + 1) & 1);
        compute(c & 1);
        __syncthreads();
    }

    // ---- epilogue ----
#pragma unroll
    for (int mf = 0; mf < 2; mf++) {
        int r0 = Mbase + wm * 32 + mf * 16 + (lane >> 2);
#pragma unroll
        for (int nf = 0; nf < NF; nf++) {
            int cc = nbase + wn * NF * 8 + nf * 8 + (lane & 3) * 2;
#pragma unroll
            for (int hh = 0; hh < 2; hh++) {
                int r = r0 + hh * 8;
                if (r >= N_NODES) continue;
                float x = acc[mf][nf][hh * 2], y = acc[mf][nf][hh * 2 + 1];
                if (EPI == 0) {
                    if (cc < 128) {
                        float2 o = make_float2(fmaxf(x + __ldg(&g_bias192[cc]), 0.0f),
                                               fmaxf(y + __ldg(&g_bias192[cc + 1]), 0.0f));
                        *(float2*)&g_h[(size_t)r * 128 + cc] = o;
                    } else if (cc < 168) {
                        float2 o = make_float2(x + __ldg(&g_bias192[cc]),
                                               y + __ldg(&g_bias192[cc + 1]));
                        *(float2*)&g_wide[(size_t)r * 40 + (cc - 128)] = o;
                    } else if (cc == 168) {
                        float l0 = x + __ldg(&g_bias192[168]);
                        float l1 = y + __ldg(&g_bias192[169]);
                        g_attn0[r] = 1.0f / (1.0f + expf(l1 - l0));
                    }
                } else {
                    g_tmph[(size_t)r * 64 + (cc >> 1)] = __floats2half2_rn(x, y);
                }
            }
        }
    }
}

// ---------------- aggregation: warp/node, fp16 features ----------------
__global__ __launch_bounds__(256) void k_aggregate(const float* __restrict__ bias,
                                                   float* __restrict__ outH) {
    int n = (blockIdx.x * blockDim.x + threadIdx.x) >> 5;
    int lane = threadIdx.x & 31;
    if (n >= N_NODES) return;
    float di = g_dinv[n];
    float s = di * di;
    uint2 tr = ((const uint2*)(g_tmph + (size_t)n * 64))[lane];
    float2 f0 = __half22float2(*(__half2*)&tr.x);
    float2 f1 = __half22float2(*(__half2*)&tr.y);
    float4 acc = make_float4(f0.x * s, f0.y * s, f1.x * s, f1.y * s);
    int st = g_offsets[n];
    int en = st + g_counts[n];
    for (int p = st; p < en; p++) {
        int r = g_csr_row[p];
        float v = g_csr_val[p];
        uint2 t = ((const uint2*)(g_tmph + (size_t)r * 64))[lane];
        float2 a = __half22float2(*(__half2*)&t.x);
        float2 b = __half22float2(*(__half2*)&t.y);
        acc.x += v * a.x; acc.y += v * a.y; acc.z += v * b.x; acc.w += v * b.y;
    }
    float4 b = ((const float4*)bias)[lane];
    acc.x = fmaxf(acc.x + b.x, 0.0f);
    acc.y = fmaxf(acc.y + b.y, 0.0f);
    acc.z = fmaxf(acc.z + b.z, 0.0f);
    acc.w = fmaxf(acc.w + b.w, 0.0f);
    ((float4*)(outH + (size_t)n * 128))[lane] = acc;
}

// ---------------- final skinny GEMM ----------------
__global__ __launch_bounds__(256) void gemm_final(const float* __restrict__ A,
                                                  const float* __restrict__ b2,
                                                  float* __restrict__ out) {
    __shared__ float As[16][68];
    __shared__ float Bs[16][48];
    const int tid = threadIdx.x;
    const int tx = tid & 15, ty = tid >> 4;
    const int m0 = blockIdx.x * 64;
    float acc[4][3];
#pragma unroll
    for (int i = 0; i < 4; i++)
#pragma unroll
        for (int j = 0; j < 3; j++) acc[i][j] = 0.0f;
    const int ra = tid >> 2;
    const int ca = (tid & 3) << 2;
    for (int k0 = 0; k0 < H_DIM; k0 += 16) {
        {
            int m = m0 + ra;
            float4 v = make_float4(0.f, 0.f, 0.f, 0.f);
            if (m < N_NODES) v = *(const float4*)(A + (size_t)m * H_DIM + k0 + ca);
            As[ca + 0][ra] = v.x; As[ca + 1][ra] = v.y;
            As[ca + 2][ra] = v.z; As[ca + 3][ra] = v.w;
        }
        if (tid < 192) {
            int kk = tid / 12;
            int nn = (tid % 12) * 4;
            *(float4*)&Bs[kk][nn] = *(const float4*)(g_W2p + (size_t)(k0 + kk) * 48 + nn);
        }
        __syncthreads();
#pragma unroll
        for (int kk = 0; kk < 16; kk++) {
            float a[4], b[3];
#pragma unroll
            for (int i = 0; i < 4; i++) a[i] = As[kk][ty * 4 + i];
#pragma unroll
            for (int j = 0; j < 3; j++) b[j] = Bs[kk][tx * 3 + j];
#pragma unroll
            for (int i = 0; i < 4; i++)
#pragma unroll
                for (int j = 0; j < 3; j++) acc[i][j] += a[i] * b[j];
        }
        __syncthreads();
    }
#pragma unroll
    for (int i = 0; i < 4; i++) {
        int m = m0 + ty * 4 + i;
        if (m >= N_NODES) continue;
        float a0 = g_attn0[m];
        float a1 = 1.0f - a0;
#pragma unroll
        for (int j = 0; j < 3; j++) {
            int c = tx * 3 + j;
            if (c < 40) {
                float deep = acc[i][j] + b2[c];
                out[(size_t)m * 40 + c] = deep * a0 + g_wide[(size_t)m * 40 + c] * a1;
            }
        }
    }
}

// ---------------- launch ----------------
extern "C" void kernel_launch(void* const* d_in, const int* in_sizes, int n_in,
                              void* d_out, int out_size)
{
    const float* x   = (const float*)d_in[0];
    const void*  ei  = d_in[1];
    const float* ew  = (const float*)d_in[2];
    const float* W1  = (const float*)d_in[3];
    const float* b1  = (const float*)d_in[4];
    const float* Wc1 = (const float*)d_in[5];
    const float* bc1 = (const float*)d_in[6];
    const float* Wc2 = (const float*)d_in[7];
    const float* bc2 = (const float*)d_in[8];
    const float* W2  = (const float*)d_in[9];
    const float* b2  = (const float*)d_in[10];
    const float* Ww  = (const float*)d_in[11];
    const float* bw  = (const float*)d_in[12];
    const float* Wa  = (const float*)d_in[13];
    const float* ba  = (const float*)d_in[14];
    float* out = (float*)d_out;

    float* h;
    unsigned short *Bl1, *Bc1, *Bc2;
    cudaGetSymbolAddress((void**)&h,   g_h);
    cudaGetSymbolAddress((void**)&Bl1, g_Bl1);
    cudaGetSymbolAddress((void**)&Bc1, g_Bc1);
    cudaGetSymbolAddress((void**)&Bc2, g_Bc2);

    const int SM_L1 = (128 + 96) * 72 * 2 * 2;   // 64512
    const int SM_CV = (128 + 64) * 72 * 2 * 2;   // 55296
    cudaFuncSetAttribute(gemm_mma<6, 1536, 0>,
                         cudaFuncAttributeMaxDynamicSharedMemorySize, SM_L1);
    cudaFuncSetAttribute(gemm_mma<4, 384, 1>,
                         cudaFuncAttributeMaxDynamicSharedMemorySize, SM_CV);

    const int EB = (E_EDGES + 255) / 256;
    const int NB = (N_NODES + 255) / 256;
    const int GB = (N_NODES + 127) / 128;      // 782

    k_detect<<<1, 64>>>((const unsigned*)ei);
    k_init<<<NB, 256>>>();
    k_pack<<<(H_DIM * 48 + 255) / 256, 256>>>(W2, b1, bw, ba);
    k_packB_l1<<<(192 * 512 + 255) / 256, 256>>>(W1, Ww, Wa);
    k_packB_conv<<<(128 * 128 + 255) / 256, 256>>>(Wc1, Bc1);
    k_packB_conv<<<(128 * 128 + 255) / 256, 256>>>(Wc2, Bc2);
    k_edge_deg<<<EB, 256>>>(ei, ew);
    k_rsqrt<<<NB, 256>>>();
    k_scan1<<<25, 256>>>();
    k_scan2<<<1, 1>>>();
    k_scan3<<<NB, 256>>>();
    k_place<<<EB, 256>>>(ei, ew);

    // fused layer1: h=relu(xW1+b1), wide=xWw+bw, attn logits
    gemm_mma<6, 1536, 0><<<dim3(GB, 2), 256, SM_L1>>>(x, Bl1, F_INDIM);
    // conv1
    gemm_mma<4, 384, 1><<<dim3(GB, 2), 256, SM_CV>>>(h, Bc1, H_DIM);
    k_aggregate<<<(N_NODES * 32 + 255) / 256, 256>>>(bc1, h);
    // conv2
    gemm_mma<4, 384, 1><<<dim3(GB, 2), 256, SM_CV>>>(h, Bc2, H_DIM);
    k_aggregate<<<(N_NODES * 32 + 255) / 256, 256>>>(bc2, h);
    // final
    gemm_final<<<(N_NODES + 63) / 64, 256>>>(h, b2, out);
}

// round 5
// speedup vs baseline: 1.0936x; 1.0936x over previous
#include <cuda_runtime.h>
#include <cuda_fp16.h>
#include <cstdint>

#define N_NODES 100000
#define E_EDGES 3200000
#define F_INDIM 512
#define H_DIM   128
#define C_OUT   40

typedef unsigned long long ull;

// ---------------- device scratch ----------------
__device__ __align__(16) float   g_h[N_NODES * H_DIM];
__device__ __align__(16) __half2 g_tmph[N_NODES * 64];
__device__ __align__(16) float   g_wide[N_NODES * C_OUT];
__device__ __align__(16) float   g_logits[N_NODES * 2];
__device__ float g_dinv[N_NODES];
__device__ int   g_counts[N_NODES];
__device__ int   g_offsets[N_NODES];
__device__ int   g_cursor[N_NODES];
__device__ int   g_csr_row[E_EDGES];
__device__ float g_csr_val[E_EDGES];
__device__ int   g_partials[32];
__device__ int   g_is64;
__device__ __align__(16) float g_W2p[H_DIM * 48];
__device__ __align__(16) float g_bias192[192];
// duplicated-pair B operands: [k][n] stored as (v,v)
__device__ __align__(16) float2 g_B1d[F_INDIM * 192];
__device__ __align__(16) float2 g_Bc1d[H_DIM * H_DIM];
__device__ __align__(16) float2 g_Bc2d[H_DIM * H_DIM];

// ---------------- dtype detect / edge prep ----------------
__global__ void k_detect(const unsigned* __restrict__ ei_raw) {
    if (threadIdx.x == 0) g_is64 = 1;
    __syncthreads();
    unsigned v = ei_raw[2 * (threadIdx.x * 997 + 1) + 1];
    if (v != 0) atomicAnd(&g_is64, 0);
}
__device__ __forceinline__ void load_edge(const void* ei, int e, int is64, int& row, int& col) {
    if (is64) {
        const long long* p = (const long long*)ei;
        row = (int)p[e]; col = (int)p[E_EDGES + e];
    } else {
        const int* p = (const int*)ei;
        row = p[e]; col = p[E_EDGES + e];
    }
}
__global__ void k_init() {
    int n = blockIdx.x * blockDim.x + threadIdx.x;
    if (n < N_NODES) { g_dinv[n] = 1.0f; g_counts[n] = 0; }
}
__global__ void k_edge_deg(const void* __restrict__ ei, const float* __restrict__ ew) {
    int e = blockIdx.x * blockDim.x + threadIdx.x;
    if (e >= E_EDGES) return;
    int row, col;
    load_edge(ei, e, g_is64, row, col);
    atomicAdd(&g_dinv[col], ew[e]);
    atomicAdd(&g_counts[col], 1);
}
__global__ void k_rsqrt() {
    int n = blockIdx.x * blockDim.x + threadIdx.x;
    if (n < N_NODES) g_dinv[n] = rsqrtf(g_dinv[n]);
}
__global__ void k_scan1() {
    int t = threadIdx.x;
    int base = blockIdx.x * 4096 + t * 16;
    int vals[16]; int tot = 0;
#pragma unroll
    for (int i = 0; i < 16; i++) {
        int idx = base + i;
        int v = (idx < N_NODES) ? g_counts[idx] : 0;
        vals[i] = v; tot += v;
    }
    int lane = t & 31, w = t >> 5;
    int inc = tot;
#pragma unroll
    for (int o = 1; o < 32; o <<= 1) {
        int x = __shfl_up_sync(0xffffffffu, inc, o);
        if (lane >= o) inc += x;
    }
    __shared__ int wsum[8], wexc[8];
    if (lane == 31) wsum[w] = inc;
    __syncthreads();
    if (t == 0) {
        int run = 0;
        for (int i = 0; i < 8; i++) { wexc[i] = run; run += wsum[i]; }
        g_partials[blockIdx.x] = run;
    }
    __syncthreads();
    int run = wexc[w] + inc - tot;
#pragma unroll
    for (int i = 0; i < 16; i++) {
        int idx = base + i;
        if (idx < N_NODES) g_offsets[idx] = run;
        run += vals[i];
    }
}
__global__ void k_scan2() {
    int run = 0;
    for (int b = 0; b < 25; b++) { int v = g_partials[b]; g_partials[b] = run; run += v; }
}
__global__ void k_scan3() {
    int idx = blockIdx.x * blockDim.x + threadIdx.x;
    if (idx < N_NODES) {
        int o = g_offsets[idx] + g_partials[idx / 4096];
        g_offsets[idx] = o;
        g_cursor[idx] = o;
    }
}
__global__ void k_place(const void* __restrict__ ei, const float* __restrict__ ew) {
    int e = blockIdx.x * blockDim.x + threadIdx.x;
    if (e >= E_EDGES) return;
    int row, col;
    load_edge(ei, e, g_is64, row, col);
    int p = atomicAdd(&g_cursor[col], 1);
    g_csr_row[p] = row;
    g_csr_val[p] = g_dinv[row] * ew[e] * g_dinv[col];
}

// ---------------- weight packing (duplicated pairs) ----------------
__global__ void k_packB_l1(const float* __restrict__ W1, const float* __restrict__ Ww,
                           const float* __restrict__ Wa) {
    int idx = blockIdx.x * blockDim.x + threadIdx.x;
    if (idx >= F_INDIM * 192) return;
    int k = idx / 192, n = idx % 192;
    float v = 0.0f;
    if (n < 128) v = W1[k * 128 + n];
    else if (n < 168) v = Ww[k * 40 + (n - 128)];
    else if (n < 170) v = Wa[k * 2 + (n - 168)];
    g_B1d[idx] = make_float2(v, v);
}
__global__ void k_packB_c(const float* __restrict__ W, float2* __restrict__ dst) {
    int idx = blockIdx.x * blockDim.x + threadIdx.x;
    if (idx >= H_DIM * H_DIM) return;
    float v = W[idx];
    dst[idx] = make_float2(v, v);
}
__global__ void k_pack(const float* __restrict__ W2, const float* __restrict__ b1,
                       const float* __restrict__ bw, const float* __restrict__ ba) {
    int i = blockIdx.x * blockDim.x + threadIdx.x;
    if (i < H_DIM * 48) {
        int k = i / 48, c = i % 48;
        g_W2p[i] = (c < 40) ? W2[k * 40 + c] : 0.0f;
    }
    if (i < 192)
        g_bias192[i] = (i < 128) ? b1[i] : ((i < 168) ? bw[i - 128] : ((i < 170) ? ba[i - 168] : 0.0f));
}

// ---------------- FFMA2 (f32x2) GEMM ----------------
// CTA: 128 M x NCOLS N, 256 threads = (tx 16) x (ty 16).
// Thread: 8 M (4 pairs) x NPT cols (col = tx + 16j).
// A fp32 [M,KTOT]; B duplicated float2 [KTOT][NCOLS].
// EPI 0: fused layer1 (h relu <128, wide 128-167, raw logits 168-169)
// EPI 1: conv -> g_tmph fp16
#define FMA2(c, a, b) asm("fma.rn.f32x2 %0, %1, %2, %0;" : "+l"(c) : "l"(a), "l"(b))

template<int NCOLS, int EPI, int OCC>
__global__ __launch_bounds__(256, OCC) void gemm_f2(
    const float* __restrict__ A, const float2* __restrict__ Bd, int KTOT)
{
    constexpr int NPT = NCOLS / 16;
    extern __shared__ __align__(16) char smem[];
    float* As = (float*)smem;                         // [16][132]
    ull* Bs = (ull*)(smem + 8448);                    // [2][16*NCOLS]
    const int tid = threadIdx.x;
    const int tx = tid & 15, ty = tid >> 4;
    const int m0 = blockIdx.x * 128;
    const int CH = KTOT / 16;

    ull acc[4][NPT];
#pragma unroll
    for (int mp = 0; mp < 4; mp++)
#pragma unroll
        for (int j = 0; j < NPT; j++) acc[mp][j] = 0ull;

    const int ra = tid >> 2, ca = (tid & 3) << 2;
    float4 pfA[2];
    ull pfB[NPT];

    auto ldgA = [&](int c) {
#pragma unroll
        for (int i = 0; i < 2; i++) {
            int m = ra + 64 * i;
            pfA[i] = (m0 + m < N_NODES)
                   ? *(const float4*)(A + (size_t)(m0 + m) * KTOT + c * 16 + ca)
                   : make_float4(0.f, 0.f, 0.f, 0.f);
        }
    };
    auto ldgB = [&](int c) {
        const ull* src = (const ull*)(Bd + (size_t)c * 16 * NCOLS);
#pragma unroll
        for (int j = 0; j < NPT; j++) pfB[j] = src[tid + 256 * j];
    };
    auto stsA = [&]() {
#pragma unroll
        for (int i = 0; i < 2; i++) {
            int m = ra + 64 * i;
            As[(ca + 0) * 132 + m] = pfA[i].x;
            As[(ca + 1) * 132 + m] = pfA[i].y;
            As[(ca + 2) * 132 + m] = pfA[i].z;
            As[(ca + 3) * 132 + m] = pfA[i].w;
        }
    };
    auto stsB = [&](int buf) {
        ull* dst = Bs + buf * (16 * NCOLS);
#pragma unroll
        for (int j = 0; j < NPT; j++) dst[tid + 256 * j] = pfB[j];
    };

    ldgA(0); ldgB(0);
    stsA(); stsB(0);
    __syncthreads();

    for (int c = 0; c < CH; c++) {
        const int buf = c & 1;
        if (c + 1 < CH) { ldgA(c + 1); ldgB(c + 1); }
        const ull* Bb = Bs + buf * (16 * NCOLS);
#pragma unroll
        for (int kk = 0; kk < 16; kk++) {
            ull av[4];
#pragma unroll
            for (int mp = 0; mp < 4; mp++)
                av[mp] = *(const ull*)&As[kk * 132 + ty * 8 + 2 * mp];
#pragma unroll
            for (int j = 0; j < NPT; j++) {
                ull bv = Bb[kk * NCOLS + tx + 16 * j];
#pragma unroll
                for (int mp = 0; mp < 4; mp++) FMA2(acc[mp][j], av[mp], bv);
            }
        }
        __syncthreads();
        if (c + 1 < CH) { stsA(); stsB(buf ^ 1); }
        __syncthreads();
    }

    // ---- epilogue ----
    if (EPI == 0) {
#pragma unroll
        for (int mp = 0; mp < 4; mp++) {
            int r = m0 + ty * 8 + 2 * mp;
#pragma unroll
            for (int j = 0; j < NPT; j++) {
                int col = tx + 16 * j;
                if (col >= 170) continue;
                uint2 u = *(uint2*)&acc[mp][j];
                float b = __ldg(&g_bias192[col]);
                float vlo = __uint_as_float(u.x) + b;
                float vhi = __uint_as_float(u.y) + b;
#pragma unroll
                for (int hh = 0; hh < 2; hh++) {
                    int rr = r + hh;
                    if (rr >= N_NODES) continue;
                    float v = hh ? vhi : vlo;
                    if (col < 128)      g_h[(size_t)rr * 128 + col] = fmaxf(v, 0.0f);
                    else if (col < 168) g_wide[(size_t)rr * 40 + (col - 128)] = v;
                    else                g_logits[2 * rr + (col - 168)] = v;
                }
            }
        }
    } else {
        __half* st = (__half*)smem;   // [128][136]
#pragma unroll
        for (int mp = 0; mp < 4; mp++) {
            int lr = ty * 8 + 2 * mp;
#pragma unroll
            for (int j = 0; j < NPT; j++) {
                int col = tx + 16 * j;
                uint2 u = *(uint2*)&acc[mp][j];
                st[lr * 136 + col]       = __float2half(__uint_as_float(u.x));
                st[(lr + 1) * 136 + col] = __float2half(__uint_as_float(u.y));
            }
        }
        __syncthreads();
        const int m = tid >> 1, seg = tid & 1;
        if (m0 + m < N_NODES) {
            uint4* dst = (uint4*)g_tmph + (size_t)(m0 + m) * 16 + seg * 8;
            const __half* src = st + m * 136 + seg * 64;
#pragma unroll
            for (int q = 0; q < 8; q++) dst[q] = *(const uint4*)(src + q * 8);
        }
    }
}

// ---------------- aggregation: warp/node, fp16 features ----------------
__global__ __launch_bounds__(256) void k_aggregate(const float* __restrict__ bias,
                                                   float* __restrict__ outH) {
    int n = (blockIdx.x * blockDim.x + threadIdx.x) >> 5;
    int lane = threadIdx.x & 31;
    if (n >= N_NODES) return;
    float di = g_dinv[n];
    float s = di * di;
    uint2 tr = ((const uint2*)(g_tmph + (size_t)n * 64))[lane];
    float2 f0 = __half22float2(*(__half2*)&tr.x);
    float2 f1 = __half22float2(*(__half2*)&tr.y);
    float4 acc = make_float4(f0.x * s, f0.y * s, f1.x * s, f1.y * s);
    int st = g_offsets[n];
    int en = st + g_counts[n];
    for (int p = st; p < en; p++) {
        int r = g_csr_row[p];
        float v = g_csr_val[p];
        uint2 t = ((const uint2*)(g_tmph + (size_t)r * 64))[lane];
        float2 a = __half22float2(*(__half2*)&t.x);
        float2 b = __half22float2(*(__half2*)&t.y);
        acc.x += v * a.x; acc.y += v * a.y; acc.z += v * b.x; acc.w += v * b.y;
    }
    float4 b = ((const float4*)bias)[lane];
    acc.x = fmaxf(acc.x + b.x, 0.0f);
    acc.y = fmaxf(acc.y + b.y, 0.0f);
    acc.z = fmaxf(acc.z + b.z, 0.0f);
    acc.w = fmaxf(acc.w + b.w, 0.0f);
    ((float4*)(outH + (size_t)n * 128))[lane] = acc;
}

// ---------------- final skinny GEMM ----------------
__global__ __launch_bounds__(256) void gemm_final(const float* __restrict__ A,
                                                  const float* __restrict__ b2,
                                                  float* __restrict__ out) {
    __shared__ float As[16][68];
    __shared__ float Bs[16][48];
    const int tid = threadIdx.x;
    const int tx = tid & 15, ty = tid >> 4;
    const int m0 = blockIdx.x * 64;
    float acc[4][3];
#pragma unroll
    for (int i = 0; i < 4; i++)
#pragma unroll
        for (int j = 0; j < 3; j++) acc[i][j] = 0.0f;
    const int ra = tid >> 2;
    const int ca = (tid & 3) << 2;
    for (int k0 = 0; k0 < H_DIM; k0 += 16) {
        {
            int m = m0 + ra;
            float4 v = make_float4(0.f, 0.f, 0.f, 0.f);
            if (m < N_NODES) v = *(const float4*)(A + (size_t)m * H_DIM + k0 + ca);
            As[ca + 0][ra] = v.x; As[ca + 1][ra] = v.y;
            As[ca + 2][ra] = v.z; As[ca + 3][ra] = v.w;
        }
        if (tid < 192) {
            int kk = tid / 12;
            int nn = (tid % 12) * 4;
            *(float4*)&Bs[kk][nn] = *(const float4*)(g_W2p + (size_t)(k0 + kk) * 48 + nn);
        }
        __syncthreads();
#pragma unroll
        for (int kk = 0; kk < 16; kk++) {
            float a[4], b[3];
#pragma unroll
            for (int i = 0; i < 4; i++) a[i] = As[kk][ty * 4 + i];
#pragma unroll
            for (int j = 0; j < 3; j++) b[j] = Bs[kk][tx * 3 + j];
#pragma unroll
            for (int i = 0; i < 4; i++)
#pragma unroll
                for (int j = 0; j < 3; j++) acc[i][j] += a[i] * b[j];
        }
        __syncthreads();
    }
#pragma unroll
    for (int i = 0; i < 4; i++) {
        int m = m0 + ty * 4 + i;
        if (m >= N_NODES) continue;
        float l0 = g_logits[2 * m], l1 = g_logits[2 * m + 1];
        float a0 = 1.0f / (1.0f + expf(l1 - l0));
        float a1 = 1.0f - a0;
#pragma unroll
        for (int j = 0; j < 3; j++) {
            int c = tx * 3 + j;
            if (c < 40) {
                float deep = acc[i][j] + b2[c];
                out[(size_t)m * 40 + c] = deep * a0 + g_wide[(size_t)m * 40 + c] * a1;
            }
        }
    }
}

// ---------------- launch ----------------
extern "C" void kernel_launch(void* const* d_in, const int* in_sizes, int n_in,
                              void* d_out, int out_size)
{
    const float* x   = (const float*)d_in[0];
    const void*  ei  = d_in[1];
    const float* ew  = (const float*)d_in[2];
    const float* W1  = (const float*)d_in[3];
    const float* b1  = (const float*)d_in[4];
    const float* Wc1 = (const float*)d_in[5];
    const float* bc1 = (const float*)d_in[6];
    const float* Wc2 = (const float*)d_in[7];
    const float* bc2 = (const float*)d_in[8];
    const float* W2  = (const float*)d_in[9];
    const float* b2  = (const float*)d_in[10];
    const float* Ww  = (const float*)d_in[11];
    const float* bw  = (const float*)d_in[12];
    const float* Wa  = (const float*)d_in[13];
    const float* ba  = (const float*)d_in[14];
    float* out = (float*)d_out;

    float* h;
    float2 *B1d, *Bc1d, *Bc2d;
    cudaGetSymbolAddress((void**)&h,    g_h);
    cudaGetSymbolAddress((void**)&B1d,  g_B1d);
    cudaGetSymbolAddress((void**)&Bc1d, g_Bc1d);
    cudaGetSymbolAddress((void**)&Bc2d, g_Bc2d);

    const int SM_L1 = 8448 + 2 * 16 * 192 * 8;   // 57600
    const int SM_CV = 8448 + 2 * 16 * 128 * 8;   // 41216 (>= 128*136*2 staging)
    cudaFuncSetAttribute(gemm_f2<192, 0, 1>,
                         cudaFuncAttributeMaxDynamicSharedMemorySize, SM_L1);
    cudaFuncSetAttribute(gemm_f2<128, 1, 2>,
                         cudaFuncAttributeMaxDynamicSharedMemorySize, SM_CV);

    const int EB = (E_EDGES + 255) / 256;
    const int NB = (N_NODES + 255) / 256;
    const int GB = (N_NODES + 127) / 128;      // 782

    // order chosen so launch idx 3 (ncu capture slot) = fused layer-1 GEMM
    k_detect<<<1, 64>>>((const unsigned*)ei);
    k_pack<<<(H_DIM * 48 + 255) / 256, 256>>>(W2, b1, bw, ba);
    k_packB_l1<<<(F_INDIM * 192 + 255) / 256, 256>>>(W1, Ww, Wa);
    gemm_f2<192, 0, 1><<<GB, 256, SM_L1>>>(x, B1d, F_INDIM);      // idx 3

    k_init<<<NB, 256>>>();
    k_edge_deg<<<EB, 256>>>(ei, ew);
    k_rsqrt<<<NB, 256>>>();
    k_scan1<<<25, 256>>>();
    k_scan2<<<1, 1>>>();
    k_scan3<<<NB, 256>>>();
    k_place<<<EB, 256>>>(ei, ew);

    k_packB_c<<<(H_DIM * H_DIM + 255) / 256, 256>>>(Wc1, Bc1d);
    gemm_f2<128, 1, 2><<<GB, 256, SM_CV>>>(h, Bc1d, H_DIM);
    k_aggregate<<<(N_NODES * 32 + 255) / 256, 256>>>(bc1, h);

    k_packB_c<<<(H_DIM * H_DIM + 255) / 256, 256>>>(Wc2, Bc2d);
    gemm_f2<128, 1, 2><<<GB, 256, SM_CV>>>(h, Bc2d, H_DIM);
    k_aggregate<<<(N_NODES * 32 + 255) / 256, 256>>>(bc2, h);

    gemm_final<<<(N_NODES + 63) / 64, 256>>>(h, b2, out);
}

// round 6
// speedup vs baseline: 1.0961x; 1.0023x over previous
#include <cuda_runtime.h>
#include <cuda_fp16.h>
#include <cstdint>

#define N_NODES 100000
#define E_EDGES 3200000
#define F_INDIM 512
#define H_DIM   128
#define C_OUT   40

typedef unsigned long long ull;

// ---------------- device scratch ----------------
__device__ __align__(16) float   g_h[N_NODES * H_DIM];
__device__ __align__(16) __half2 g_tmph[N_NODES * 64];
__device__ __align__(16) float   g_wide[N_NODES * C_OUT];
__device__ float g_attn0[N_NODES];
__device__ float g_dinv[N_NODES];
__device__ int   g_counts[N_NODES];
__device__ int   g_offsets[N_NODES];
__device__ int   g_cursor[N_NODES];
__device__ int   g_csr_row[E_EDGES];
__device__ float g_csr_val[E_EDGES];
__device__ int   g_partials[32];
__device__ int   g_is64;
__device__ __align__(16) float g_W2p[H_DIM * 48];
__device__ __align__(16) float g_bias192[192];
__device__ __align__(16) float g_B1[F_INDIM * 192];   // plain [k][n] concat W1|Ww|Wa

// ---------------- dtype detect / edge prep ----------------
__global__ void k_detect(const unsigned* __restrict__ ei_raw) {
    if (threadIdx.x == 0) g_is64 = 1;
    __syncthreads();
    unsigned v = ei_raw[2 * (threadIdx.x * 997 + 1) + 1];
    if (v != 0) atomicAnd(&g_is64, 0);
}
__device__ __forceinline__ void load_edge(const void* ei, int e, int is64, int& row, int& col) {
    if (is64) {
        const long long* p = (const long long*)ei;
        row = (int)p[e]; col = (int)p[E_EDGES + e];
    } else {
        const int* p = (const int*)ei;
        row = p[e]; col = p[E_EDGES + e];
    }
}
__global__ void k_init() {
    int n = blockIdx.x * blockDim.x + threadIdx.x;
    if (n < N_NODES) { g_dinv[n] = 1.0f; g_counts[n] = 0; }
}
__global__ void k_edge_deg(const void* __restrict__ ei, const float* __restrict__ ew) {
    int e = blockIdx.x * blockDim.x + threadIdx.x;
    if (e >= E_EDGES) return;
    int row, col;
    load_edge(ei, e, g_is64, row, col);
    atomicAdd(&g_dinv[col], ew[e]);
    atomicAdd(&g_counts[col], 1);
}
__global__ void k_rsqrt() {
    int n = blockIdx.x * blockDim.x + threadIdx.x;
    if (n < N_NODES) g_dinv[n] = rsqrtf(g_dinv[n]);
}
__global__ void k_scan1() {
    int t = threadIdx.x;
    int base = blockIdx.x * 4096 + t * 16;
    int vals[16]; int tot = 0;
#pragma unroll
    for (int i = 0; i < 16; i++) {
        int idx = base + i;
        int v = (idx < N_NODES) ? g_counts[idx] : 0;
        vals[i] = v; tot += v;
    }
    int lane = t & 31, w = t >> 5;
    int inc = tot;
#pragma unroll
    for (int o = 1; o < 32; o <<= 1) {
        int x = __shfl_up_sync(0xffffffffu, inc, o);
        if (lane >= o) inc += x;
    }
    __shared__ int wsum[8], wexc[8];
    if (lane == 31) wsum[w] = inc;
    __syncthreads();
    if (t == 0) {
        int run = 0;
        for (int i = 0; i < 8; i++) { wexc[i] = run; run += wsum[i]; }
        g_partials[blockIdx.x] = run;
    }
    __syncthreads();
    int run = wexc[w] + inc - tot;
#pragma unroll
    for (int i = 0; i < 16; i++) {
        int idx = base + i;
        if (idx < N_NODES) g_offsets[idx] = run;
        run += vals[i];
    }
}
__global__ void k_scan2() {
    int run = 0;
    for (int b = 0; b < 25; b++) { int v = g_partials[b]; g_partials[b] = run; run += v; }
}
__global__ void k_scan3() {
    int idx = blockIdx.x * blockDim.x + threadIdx.x;
    if (idx < N_NODES) {
        int o = g_offsets[idx] + g_partials[idx / 4096];
        g_offsets[idx] = o;
        g_cursor[idx] = o;
    }
}
__global__ void k_place(const void* __restrict__ ei, const float* __restrict__ ew) {
    int e = blockIdx.x * blockDim.x + threadIdx.x;
    if (e >= E_EDGES) return;
    int row, col;
    load_edge(ei, e, g_is64, row, col);
    int p = atomicAdd(&g_cursor[col], 1);
    g_csr_row[p] = row;
    g_csr_val[p] = g_dinv[row] * ew[e] * g_dinv[col];
}

// ---------------- weight packing ----------------
__global__ void k_packB_l1(const float* __restrict__ W1, const float* __restrict__ Ww,
                           const float* __restrict__ Wa) {
    int idx = blockIdx.x * blockDim.x + threadIdx.x;
    if (idx >= F_INDIM * 192) return;
    int k = idx / 192, n = idx % 192;
    float v = 0.0f;
    if (n < 128) v = W1[k * 128 + n];
    else if (n < 168) v = Ww[k * 40 + (n - 128)];
    else if (n < 170) v = Wa[k * 2 + (n - 168)];
    g_B1[idx] = v;
}
__global__ void k_pack(const float* __restrict__ W2, const float* __restrict__ b1,
                       const float* __restrict__ bw, const float* __restrict__ ba) {
    int i = blockIdx.x * blockDim.x + threadIdx.x;
    if (i < H_DIM * 48) {
        int k = i / 48, c = i % 48;
        g_W2p[i] = (c < 40) ? W2[k * 40 + c] : 0.0f;
    }
    if (i < 192)
        g_bias192[i] = (i < 128) ? b1[i] : ((i < 168) ? bw[i - 128] : ((i < 170) ? ba[i - 168] : 0.0f));
}

// ---------------- FFMA2 GEMM, N-pair accumulators ----------------
// CTA: 128 M x NCOLS N, 256 thr = (tx 16)x(ty 16). Thread: 8 M x NP2 col-pairs.
// col pair p at (2tx+32p, +1). A SMEM pre-duplicated (a,a) ull; B SMEM plain fp32.
// EPI 0: fused layer1. EPI 1: conv -> g_tmph (direct half2).
#define FMA2(c, a, b) asm("fma.rn.f32x2 %0, %1, %2, %0;" : "+l"(c) : "l"(a), "l"(b))
#define AST 132   // ull stride per kk row of duplicated A

__device__ __forceinline__ ull dup_f32(float v) {
    uint32_t u = __float_as_uint(v);
    ull d;
    asm("mov.b64 %0, {%1, %1};" : "=l"(d) : "r"(u));
    return d;
}

template<int NCOLS, int EPI, int OCC>
__global__ __launch_bounds__(256, OCC) void gemm_f2(
    const float* __restrict__ A, const float* __restrict__ B, int KTOT)
{
    constexpr int NP2 = NCOLS / 32;            // col-pairs per thread
    constexpr int BF4 = NCOLS / 64;            // float4 B-loads per thread per chunk
    extern __shared__ __align__(16) char smem[];
    ull* Asd = (ull*)smem;                               // [16][AST]
    float* Bsf = (float*)(smem + 16 * AST * 8);          // [2][16*NCOLS]
    const int tid = threadIdx.x;
    const int tx = tid & 15, ty = tid >> 4;
    const int m0 = blockIdx.x * 128;
    const int CH = KTOT / 16;

    ull acc[8][NP2];
#pragma unroll
    for (int mp = 0; mp < 8; mp++)
#pragma unroll
        for (int p = 0; p < NP2; p++) acc[mp][p] = 0ull;

    const int ra = tid >> 2, ca = (tid & 3) << 2;
    float4 pfA[2];
    float4 pfB[BF4];

    auto ldgA = [&](int c) {
#pragma unroll
        for (int i = 0; i < 2; i++) {
            int m = ra + 64 * i;
            pfA[i] = (m0 + m < N_NODES)
                   ? *(const float4*)(A + (size_t)(m0 + m) * KTOT + c * 16 + ca)
                   : make_float4(0.f, 0.f, 0.f, 0.f);
        }
    };
    auto ldgB = [&](int c) {
        const float4* src = (const float4*)(B + (size_t)c * 16 * NCOLS);
#pragma unroll
        for (int j = 0; j < BF4; j++) pfB[j] = src[tid + 256 * j];
    };
    auto stsA = [&]() {
#pragma unroll
        for (int i = 0; i < 2; i++) {
            int m = ra + 64 * i;
            Asd[(ca + 0) * AST + m] = dup_f32(pfA[i].x);
            Asd[(ca + 1) * AST + m] = dup_f32(pfA[i].y);
            Asd[(ca + 2) * AST + m] = dup_f32(pfA[i].z);
            Asd[(ca + 3) * AST + m] = dup_f32(pfA[i].w);
        }
    };
    auto stsB = [&](int buf) {
        float4* dst = (float4*)(Bsf + buf * (16 * NCOLS));
#pragma unroll
        for (int j = 0; j < BF4; j++) dst[tid + 256 * j] = pfB[j];
    };

    ldgA(0); ldgB(0);
    stsA(); stsB(0);
    __syncthreads();

    for (int c = 0; c < CH; c++) {
        const int buf = c & 1;
        if (c + 1 < CH) { ldgA(c + 1); ldgB(c + 1); }
        const float* Bb = Bsf + buf * (16 * NCOLS);
#pragma unroll
        for (int kk = 0; kk < 16; kk++) {
            ull av[8];
#pragma unroll
            for (int mp = 0; mp < 8; mp++)
                av[mp] = Asd[kk * AST + ty * 8 + mp];
#pragma unroll
            for (int p = 0; p < NP2; p++) {
                ull bv = *(const ull*)(Bb + kk * NCOLS + 2 * tx + 32 * p);
#pragma unroll
                for (int mp = 0; mp < 8; mp++) FMA2(acc[mp][p], av[mp], bv);
            }
        }
        __syncthreads();
        if (c + 1 < CH) { stsA(); stsB(buf ^ 1); }
        __syncthreads();
    }

    // ---- epilogue: acc[mp][p] = row m0+ty*8+mp, cols (2tx+32p, +1) ----
#pragma unroll
    for (int mp = 0; mp < 8; mp++) {
        const int r = m0 + ty * 8 + mp;
        if (r >= N_NODES) continue;
#pragma unroll
        for (int p = 0; p < NP2; p++) {
            const int col = 2 * tx + 32 * p;
            uint2 u = *(uint2*)&acc[mp][p];
            float x = __uint_as_float(u.x), y = __uint_as_float(u.y);
            if (EPI == 0) {
                float2 bb = *(const float2*)&g_bias192[col];
                x += bb.x; y += bb.y;
                if (p < 4) {
                    float2 o = make_float2(fmaxf(x, 0.0f), fmaxf(y, 0.0f));
                    *(float2*)&g_h[(size_t)r * 128 + col] = o;
                } else if (p == 4) {
                    *(float2*)&g_wide[(size_t)r * 40 + (col - 128)] = make_float2(x, y);
                } else {
                    if (tx < 4)
                        *(float2*)&g_wide[(size_t)r * 40 + (col - 128)] = make_float2(x, y);
                    else if (tx == 4)
                        g_attn0[r] = 1.0f / (1.0f + expf(y - x));
                }
            } else {
                g_tmph[(size_t)r * 64 + tx + 16 * p] = __floats2half2_rn(x, y);
            }
        }
    }
}

// ---------------- aggregation: warp/node, fp16 features ----------------
__global__ __launch_bounds__(256) void k_aggregate(const float* __restrict__ bias,
                                                   float* __restrict__ outH) {
    int n = (blockIdx.x * blockDim.x + threadIdx.x) >> 5;
    int lane = threadIdx.x & 31;
    if (n >= N_NODES) return;
    float di = g_dinv[n];
    float s = di * di;
    uint2 tr = ((const uint2*)(g_tmph + (size_t)n * 64))[lane];
    float2 f0 = __half22float2(*(__half2*)&tr.x);
    float2 f1 = __half22float2(*(__half2*)&tr.y);
    float4 acc = make_float4(f0.x * s, f0.y * s, f1.x * s, f1.y * s);
    int st = g_offsets[n];
    int en = st + g_counts[n];
    for (int p = st; p < en; p++) {
        int r = g_csr_row[p];
        float v = g_csr_val[p];
        uint2 t = ((const uint2*)(g_tmph + (size_t)r * 64))[lane];
        float2 a = __half22float2(*(__half2*)&t.x);
        float2 b = __half22float2(*(__half2*)&t.y);
        acc.x += v * a.x; acc.y += v * a.y; acc.z += v * b.x; acc.w += v * b.y;
    }
    float4 b = ((const float4*)bias)[lane];
    acc.x = fmaxf(acc.x + b.x, 0.0f);
    acc.y = fmaxf(acc.y + b.y, 0.0f);
    acc.z = fmaxf(acc.z + b.z, 0.0f);
    acc.w = fmaxf(acc.w + b.w, 0.0f);
    ((float4*)(outH + (size_t)n * 128))[lane] = acc;
}

// ---------------- final skinny GEMM ----------------
__global__ __launch_bounds__(256) void gemm_final(const float* __restrict__ A,
                                                  const float* __restrict__ b2,
                                                  float* __restrict__ out) {
    __shared__ float As[16][68];
    __shared__ float Bs[16][48];
    const int tid = threadIdx.x;
    const int tx = tid & 15, ty = tid >> 4;
    const int m0 = blockIdx.x * 64;
    float acc[4][3];
#pragma unroll
    for (int i = 0; i < 4; i++)
#pragma unroll
        for (int j = 0; j < 3; j++) acc[i][j] = 0.0f;
    const int ra = tid >> 2;
    const int ca = (tid & 3) << 2;
    for (int k0 = 0; k0 < H_DIM; k0 += 16) {
        {
            int m = m0 + ra;
            float4 v = make_float4(0.f, 0.f, 0.f, 0.f);
            if (m < N_NODES) v = *(const float4*)(A + (size_t)m * H_DIM + k0 + ca);
            As[ca + 0][ra] = v.x; As[ca + 1][ra] = v.y;
            As[ca + 2][ra] = v.z; As[ca + 3][ra] = v.w;
        }
        if (tid < 192) {
            int kk = tid / 12;
            int nn = (tid % 12) * 4;
            *(float4*)&Bs[kk][nn] = *(const float4*)(g_W2p + (size_t)(k0 + kk) * 48 + nn);
        }
        __syncthreads();
#pragma unroll
        for (int kk = 0; kk < 16; kk++) {
            float a[4], b[3];
#pragma unroll
            for (int i = 0; i < 4; i++) a[i] = As[kk][ty * 4 + i];
#pragma unroll
            for (int j = 0; j < 3; j++) b[j] = Bs[kk][tx * 3 + j];
#pragma unroll
            for (int i = 0; i < 4; i++)
#pragma unroll
                for (int j = 0; j < 3; j++) acc[i][j] += a[i] * b[j];
        }
        __syncthreads();
    }
#pragma unroll
    for (int i = 0; i < 4; i++) {
        int m = m0 + ty * 4 + i;
        if (m >= N_NODES) continue;
        float a0 = g_attn0[m];
        float a1 = 1.0f - a0;
#pragma unroll
        for (int j = 0; j < 3; j++) {
            int c = tx * 3 + j;
            if (c < 40) {
                float deep = acc[i][j] + b2[c];
                out[(size_t)m * 40 + c] = deep * a0 + g_wide[(size_t)m * 40 + c] * a1;
            }
        }
    }
}

// ---------------- launch ----------------
extern "C" void kernel_launch(void* const* d_in, const int* in_sizes, int n_in,
                              void* d_out, int out_size)
{
    const float* x   = (const float*)d_in[0];
    const void*  ei  = d_in[1];
    const float* ew  = (const float*)d_in[2];
    const float* W1  = (const float*)d_in[3];
    const float* b1  = (const float*)d_in[4];
    const float* Wc1 = (const float*)d_in[5];
    const float* bc1 = (const float*)d_in[6];
    const float* Wc2 = (const float*)d_in[7];
    const float* bc2 = (const float*)d_in[8];
    const float* W2  = (const float*)d_in[9];
    const float* b2  = (const float*)d_in[10];
    const float* Ww  = (const float*)d_in[11];
    const float* bw  = (const float*)d_in[12];
    const float* Wa  = (const float*)d_in[13];
    const float* ba  = (const float*)d_in[14];
    float* out = (float*)d_out;

    float *h, *B1;
    cudaGetSymbolAddress((void**)&h,  g_h);
    cudaGetSymbolAddress((void**)&B1, g_B1);

    const int SM_L1 = 16 * AST * 8 + 2 * 16 * 192 * 4;   // 16896 + 24576 = 41472
    const int SM_CV = 16 * AST * 8 + 2 * 16 * 128 * 4;   // 16896 + 16384 = 33280
    cudaFuncSetAttribute(gemm_f2<192, 0, 1>,
                         cudaFuncAttributeMaxDynamicSharedMemorySize, SM_L1);
    cudaFuncSetAttribute(gemm_f2<128, 1, 2>,
                         cudaFuncAttributeMaxDynamicSharedMemorySize, SM_CV);

    const int EB = (E_EDGES + 255) / 256;
    const int NB = (N_NODES + 255) / 256;
    const int GB = (N_NODES + 127) / 128;      // 782

    // launch idx 3 = fused layer-1 GEMM (ncu capture slot)
    k_detect<<<1, 64>>>((const unsigned*)ei);
    k_pack<<<(H_DIM * 48 + 255) / 256, 256>>>(W2, b1, bw, ba);
    k_packB_l1<<<(F_INDIM * 192 + 255) / 256, 256>>>(W1, Ww, Wa);
    gemm_f2<192, 0, 1><<<GB, 256, SM_L1>>>(x, B1, F_INDIM);      // idx 3

    k_init<<<NB, 256>>>();
    k_edge_deg<<<EB, 256>>>(ei, ew);
    k_rsqrt<<<NB, 256>>>();
    k_scan1<<<25, 256>>>();
    k_scan2<<<1, 1>>>();
    k_scan3<<<NB, 256>>>();
    k_place<<<EB, 256>>>(ei, ew);

    gemm_f2<128, 1, 2><<<GB, 256, SM_CV>>>(h, Wc1, H_DIM);
    k_aggregate<<<(N_NODES * 32 + 255) / 256, 256>>>(bc1, h);

    gemm_f2<128, 1, 2><<<GB, 256, SM_CV>>>(h, Wc2, H_DIM);
    k_aggregate<<<(N_NODES * 32 + 255) / 256, 256>>>(bc2, h);

    gemm_final<<<(N_NODES + 63) / 64, 256>>>(h, b2, out);
}